// round 1
// baseline (speedup 1.0000x reference)
#include <cuda_runtime.h>
#include <cstddef>

#define BB 8
#define NN 2048
#define DD 512

// Scratch (static device globals: allocation-free rule)
__device__ float g_Q[(size_t)BB * NN * DD];
__device__ float g_K[(size_t)BB * NN * DD];
__device__ float g_V[(size_t)BB * NN * DD];
__device__ float g_W[(size_t)BB * NN * NN];
__device__ float g_rs[(size_t)BB * NN];

// ----------------------------------------------------------------------------
// Kernel 1: QKV projections.  y[b,n,o] = sum_d x[b,n,d]*W[o,d] + bias[o]
// A = x as [M=16384, K=512] row-major; B = W [O,K] row-major (B^T gemm).
// 128x128 tile, BK=8, 256 threads, 8x8 per-thread microtile.
// ----------------------------------------------------------------------------
__global__ __launch_bounds__(256, 2)
void qkv_kernel(const float* __restrict__ x,
                const float* __restrict__ Wq, const float* __restrict__ bq,
                const float* __restrict__ Wk, const float* __restrict__ bk,
                const float* __restrict__ Wv, const float* __restrict__ bv)
{
    const int K = DD;
    const float* Wm;
    const float* bm;
    float* out;
    if (blockIdx.z == 0)      { Wm = Wq; bm = bq; out = g_Q; }
    else if (blockIdx.z == 1) { Wm = Wk; bm = bk; out = g_K; }
    else                      { Wm = Wv; bm = bv; out = g_V; }

    const int m0 = blockIdx.x * 128;
    const int n0 = blockIdx.y * 128;

    __shared__ float As[8][128];
    __shared__ float Bs[8][128];

    const int tid = threadIdx.x;
    const int tx = tid & 15;        // 16 col-threads
    const int ty = tid >> 4;        // 16 row-threads
    const int ldRow = tid >> 1;     // 0..127
    const int ldCol = (tid & 1) * 4;

    float acc[8][8];
    #pragma unroll
    for (int i = 0; i < 8; i++)
        #pragma unroll
        for (int j = 0; j < 8; j++) acc[i][j] = 0.f;

    for (int k0 = 0; k0 < K; k0 += 8) {
        float4 av = *(const float4*)(x  + (size_t)(m0 + ldRow) * K + k0 + ldCol);
        float4 bv4 = *(const float4*)(Wm + (size_t)(n0 + ldRow) * K + k0 + ldCol);
        __syncthreads();
        As[ldCol + 0][ldRow] = av.x;  As[ldCol + 1][ldRow] = av.y;
        As[ldCol + 2][ldRow] = av.z;  As[ldCol + 3][ldRow] = av.w;
        Bs[ldCol + 0][ldRow] = bv4.x; Bs[ldCol + 1][ldRow] = bv4.y;
        Bs[ldCol + 2][ldRow] = bv4.z; Bs[ldCol + 3][ldRow] = bv4.w;
        __syncthreads();
        #pragma unroll
        for (int kk = 0; kk < 8; kk++) {
            float ra[8], rb[8];
            #pragma unroll
            for (int i = 0; i < 8; i++) ra[i] = As[kk][ty * 8 + i];
            #pragma unroll
            for (int j = 0; j < 8; j++) rb[j] = Bs[kk][tx * 8 + j];
            #pragma unroll
            for (int i = 0; i < 8; i++)
                #pragma unroll
                for (int j = 0; j < 8; j++) acc[i][j] += ra[i] * rb[j];
        }
    }

    #pragma unroll
    for (int i = 0; i < 8; i++) {
        const int row = m0 + ty * 8 + i;
        float* op = out + (size_t)row * DD + n0 + tx * 8;
        #pragma unroll
        for (int jj = 0; jj < 8; jj += 4) {
            float4 r;
            r.x = acc[i][jj + 0] + bm[n0 + tx * 8 + jj + 0];
            r.y = acc[i][jj + 1] + bm[n0 + tx * 8 + jj + 1];
            r.z = acc[i][jj + 2] + bm[n0 + tx * 8 + jj + 2];
            r.w = acc[i][jj + 3] + bm[n0 + tx * 8 + jj + 3];
            *(float4*)(op + jj) = r;
        }
    }
}

// ----------------------------------------------------------------------------
// Kernel 2: scores.  W[b,q,k] = adj[b,q,k] * exp( Q[b,q,:] . K[b,k,:] )
// GEMM A=Q [N,D], B=K [N,D] (B^T), fused mask*exp epilogue.
// ----------------------------------------------------------------------------
__global__ __launch_bounds__(256, 2)
void score_kernel(const float* __restrict__ adj)
{
    const int b  = blockIdx.z;
    const int q0 = blockIdx.x * 128;
    const int c0 = blockIdx.y * 128;
    const float* Q  = g_Q + (size_t)b * NN * DD;
    const float* Km = g_K + (size_t)b * NN * DD;

    __shared__ float As[8][128];
    __shared__ float Bs[8][128];

    const int tid = threadIdx.x;
    const int tx = tid & 15;
    const int ty = tid >> 4;
    const int ldRow = tid >> 1;
    const int ldCol = (tid & 1) * 4;

    float acc[8][8];
    #pragma unroll
    for (int i = 0; i < 8; i++)
        #pragma unroll
        for (int j = 0; j < 8; j++) acc[i][j] = 0.f;

    for (int k0 = 0; k0 < DD; k0 += 8) {
        float4 av = *(const float4*)(Q  + (size_t)(q0 + ldRow) * DD + k0 + ldCol);
        float4 bv4 = *(const float4*)(Km + (size_t)(c0 + ldRow) * DD + k0 + ldCol);
        __syncthreads();
        As[ldCol + 0][ldRow] = av.x;  As[ldCol + 1][ldRow] = av.y;
        As[ldCol + 2][ldRow] = av.z;  As[ldCol + 3][ldRow] = av.w;
        Bs[ldCol + 0][ldRow] = bv4.x; Bs[ldCol + 1][ldRow] = bv4.y;
        Bs[ldCol + 2][ldRow] = bv4.z; Bs[ldCol + 3][ldRow] = bv4.w;
        __syncthreads();
        #pragma unroll
        for (int kk = 0; kk < 8; kk++) {
            float ra[8], rb[8];
            #pragma unroll
            for (int i = 0; i < 8; i++) ra[i] = As[kk][ty * 8 + i];
            #pragma unroll
            for (int j = 0; j < 8; j++) rb[j] = Bs[kk][tx * 8 + j];
            #pragma unroll
            for (int i = 0; i < 8; i++)
                #pragma unroll
                for (int j = 0; j < 8; j++) acc[i][j] += ra[i] * rb[j];
        }
    }

    #pragma unroll
    for (int i = 0; i < 8; i++) {
        const int row = q0 + ty * 8 + i;
        const size_t base = (size_t)b * NN * NN + (size_t)row * NN + c0 + tx * 8;
        const float* ap = adj + base;
        float* wp = g_W + base;
        #pragma unroll
        for (int jj = 0; jj < 8; jj += 4) {
            float4 a4 = *(const float4*)(ap + jj);
            float4 r;
            r.x = a4.x * expf(acc[i][jj + 0]);
            r.y = a4.y * expf(acc[i][jj + 1]);
            r.z = a4.z * expf(acc[i][jj + 2]);
            r.w = a4.w * expf(acc[i][jj + 3]);
            *(float4*)(wp + jj) = r;
        }
    }
}

// ----------------------------------------------------------------------------
// Kernel 3: rowsum of W.  One warp per row.
// ----------------------------------------------------------------------------
__global__ void rowsum_kernel()
{
    const int row = blockIdx.x * (blockDim.x >> 5) + (threadIdx.x >> 5);
    const int lane = threadIdx.x & 31;
    const float* p = g_W + (size_t)row * NN;
    float s = 0.f;
    for (int c = lane * 4; c < NN; c += 128) {
        float4 v = *(const float4*)(p + c);
        s += v.x + v.y + v.z + v.w;
    }
    #pragma unroll
    for (int o = 16; o; o >>= 1) s += __shfl_xor_sync(0xffffffffu, s, o);
    if (lane == 0) g_rs[row] = s;
}

// ----------------------------------------------------------------------------
// Kernel 4: O = (W @ V) / rowsum.  GEMM A=W [N,N], B=V [N,D] (non-transposed).
// ----------------------------------------------------------------------------
__global__ __launch_bounds__(256, 2)
void out_kernel(float* __restrict__ out)
{
    const int b  = blockIdx.z;
    const int m0 = blockIdx.x * 128;
    const int n0 = blockIdx.y * 128;
    const float* A  = g_W + (size_t)b * NN * NN;
    const float* Bv = g_V + (size_t)b * NN * DD;

    __shared__ float As[8][128];
    __shared__ float Bs[8][128];

    const int tid = threadIdx.x;
    const int tx = tid & 15;
    const int ty = tid >> 4;
    const int aRow = tid >> 1;          // m index 0..127
    const int aCol = (tid & 1) * 4;     // k sub-index
    const int bRow = tid >> 5;          // k index 0..7
    const int bCol = (tid & 31) * 4;    // n index 0..127

    float acc[8][8];
    #pragma unroll
    for (int i = 0; i < 8; i++)
        #pragma unroll
        for (int j = 0; j < 8; j++) acc[i][j] = 0.f;

    for (int k0 = 0; k0 < NN; k0 += 8) {
        float4 av = *(const float4*)(A  + (size_t)(m0 + aRow) * NN + k0 + aCol);
        float4 bv4 = *(const float4*)(Bv + (size_t)(k0 + bRow) * DD + n0 + bCol);
        __syncthreads();
        As[aCol + 0][aRow] = av.x; As[aCol + 1][aRow] = av.y;
        As[aCol + 2][aRow] = av.z; As[aCol + 3][aRow] = av.w;
        *(float4*)(&Bs[bRow][bCol]) = bv4;
        __syncthreads();
        #pragma unroll
        for (int kk = 0; kk < 8; kk++) {
            float ra[8], rb[8];
            #pragma unroll
            for (int i = 0; i < 8; i++) ra[i] = As[kk][ty * 8 + i];
            #pragma unroll
            for (int j = 0; j < 8; j++) rb[j] = Bs[kk][tx * 8 + j];
            #pragma unroll
            for (int i = 0; i < 8; i++)
                #pragma unroll
                for (int j = 0; j < 8; j++) acc[i][j] += ra[i] * rb[j];
        }
    }

    #pragma unroll
    for (int i = 0; i < 8; i++) {
        const int row = m0 + ty * 8 + i;
        const float inv = 1.0f / g_rs[b * NN + row];
        float* op = out + (size_t)b * NN * DD + (size_t)row * DD + n0 + tx * 8;
        #pragma unroll
        for (int jj = 0; jj < 8; jj += 4) {
            float4 r;
            r.x = acc[i][jj + 0] * inv;
            r.y = acc[i][jj + 1] * inv;
            r.z = acc[i][jj + 2] * inv;
            r.w = acc[i][jj + 3] * inv;
            *(float4*)(op + jj) = r;
        }
    }
}

// ----------------------------------------------------------------------------
extern "C" void kernel_launch(void* const* d_in, const int* in_sizes, int n_in,
                              void* d_out, int out_size)
{
    const float* x    = (const float*)d_in[0];
    const float* adj  = (const float*)d_in[1];
    const float* Wq_w = (const float*)d_in[2];
    const float* Wq_b = (const float*)d_in[3];
    const float* Wk_w = (const float*)d_in[4];
    const float* Wk_b = (const float*)d_in[5];
    const float* Wv_w = (const float*)d_in[6];
    const float* Wv_b = (const float*)d_in[7];
    float* out = (float*)d_out;

    // 1) QKV projections: M = B*N = 16384 rows, 512 outputs, 3 matrices
    {
        dim3 grid(BB * NN / 128, DD / 128, 3);
        qkv_kernel<<<grid, 256>>>(x, Wq_w, Wq_b, Wk_w, Wk_b, Wv_w, Wv_b);
    }
    // 2) masked-exp scores
    {
        dim3 grid(NN / 128, NN / 128, BB);
        score_kernel<<<grid, 256>>>(adj);
    }
    // 3) rowsums (16384 rows, 8 warps/block)
    {
        rowsum_kernel<<<(BB * NN) / 8, 256>>>();
    }
    // 4) aggregate + normalize
    {
        dim3 grid(NN / 128, DD / 128, BB);
        out_kernel<<<grid, 256>>>(out);
    }
}

// round 2
// speedup vs baseline: 1.1827x; 1.1827x over previous
#include <cuda_runtime.h>
#include <cstddef>

#define BB 8
#define NN 2048
#define DD 512

// Scratch (static device globals: allocation-free rule)
__device__ float g_Q[(size_t)BB * NN * DD];
__device__ float g_K[(size_t)BB * NN * DD];
__device__ float g_V[(size_t)BB * NN * DD];
__device__ float g_W[(size_t)BB * NN * NN];
__device__ float g_rs[(size_t)BB * NN];

__global__ void zero_rs_kernel() {
    g_rs[blockIdx.x * 256 + threadIdx.x] = 0.f;
}

// Transposed store of a K-major 8-column slab into smem [k][m] planes.
#define XSTORE(S, v0, v1)                                           \
    do {                                                            \
        S[cb + 0][rowL] = v0.x; S[cb + 1][rowL] = v0.y;             \
        S[cb + 2][rowL] = v0.z; S[cb + 3][rowL] = v0.w;             \
        S[cb + 4][rowL] = v1.x; S[cb + 5][rowL] = v1.y;             \
        S[cb + 6][rowL] = v1.z; S[cb + 7][rowL] = v1.w;             \
    } while (0)

// 16-k-step FFMA stage from smem (conflict-free: float4 at t*4 and 64+t*4).
#define COMPUTE_STAGE(AS, BS)                                       \
    _Pragma("unroll")                                               \
    for (int kk = 0; kk < 16; kk++) {                               \
        float4 ra0 = *(const float4*)&AS[kk][ty4];                  \
        float4 ra1 = *(const float4*)&AS[kk][64 + ty4];             \
        float4 rb0 = *(const float4*)&BS[kk][tx4];                  \
        float4 rb1 = *(const float4*)&BS[kk][64 + tx4];             \
        float av[8] = {ra0.x, ra0.y, ra0.z, ra0.w,                  \
                       ra1.x, ra1.y, ra1.z, ra1.w};                 \
        float bw[8] = {rb0.x, rb0.y, rb0.z, rb0.w,                  \
                       rb1.x, rb1.y, rb1.z, rb1.w};                 \
        _Pragma("unroll")                                           \
        for (int i = 0; i < 8; i++)                                 \
            _Pragma("unroll")                                       \
            for (int j = 0; j < 8; j++)                             \
                acc[i][j] += av[i] * bw[j];                         \
    }

// ----------------------------------------------------------------------------
// Kernel 1: QKV projections. y[b,n,o] = sum_d x[b,n,d]*W[o,d] + b[o]
// ----------------------------------------------------------------------------
__global__ __launch_bounds__(256, 2)
void qkv_kernel(const float* __restrict__ x,
                const float* __restrict__ Wq, const float* __restrict__ bq,
                const float* __restrict__ Wk, const float* __restrict__ bk,
                const float* __restrict__ Wv, const float* __restrict__ bv)
{
    const float* Wm; const float* bm; float* out;
    if (blockIdx.z == 0)      { Wm = Wq; bm = bq; out = g_Q; }
    else if (blockIdx.z == 1) { Wm = Wk; bm = bk; out = g_K; }
    else                      { Wm = Wv; bm = bv; out = g_V; }

    const int m0 = blockIdx.x * 128;
    const int n0 = blockIdx.y * 128;

    __shared__ float As[2][16][128];
    __shared__ float Bs[2][16][128];

    const int tid = threadIdx.x;
    const int tx4 = (tid & 15) * 4;
    const int ty4 = (tid >> 4) * 4;
    const int rowL = tid & 127;
    const int cb = (tid >> 7) * 8;

    const float* Ag = x  + (size_t)(m0 + rowL) * DD + cb;
    const float* Bg = Wm + (size_t)(n0 + rowL) * DD + cb;

    float4 a0 = *(const float4*)(Ag);
    float4 a1 = *(const float4*)(Ag + 4);
    float4 b0 = *(const float4*)(Bg);
    float4 b1 = *(const float4*)(Bg + 4);
    XSTORE(As[0], a0, a1);
    XSTORE(Bs[0], b0, b1);
    __syncthreads();

    float acc[8][8];
    #pragma unroll
    for (int i = 0; i < 8; i++)
        #pragma unroll
        for (int j = 0; j < 8; j++) acc[i][j] = 0.f;

    int buf = 0;
    for (int k0 = 16; k0 < DD; k0 += 16) {
        a0 = *(const float4*)(Ag + k0);
        a1 = *(const float4*)(Ag + k0 + 4);
        b0 = *(const float4*)(Bg + k0);
        b1 = *(const float4*)(Bg + k0 + 4);
        COMPUTE_STAGE(As[buf], Bs[buf]);
        XSTORE(As[buf ^ 1], a0, a1);
        XSTORE(Bs[buf ^ 1], b0, b1);
        __syncthreads();
        buf ^= 1;
    }
    COMPUTE_STAGE(As[buf], Bs[buf]);

    float4 bias0 = *(const float4*)(bm + n0 + tx4);
    float4 bias1 = *(const float4*)(bm + n0 + 64 + tx4);
    #pragma unroll
    for (int i = 0; i < 8; i++) {
        const int row = m0 + (i < 4 ? ty4 + i : 64 + ty4 + i - 4);
        float* op = out + (size_t)row * DD + n0;
        float4 r0 = {acc[i][0] + bias0.x, acc[i][1] + bias0.y,
                     acc[i][2] + bias0.z, acc[i][3] + bias0.w};
        float4 r1 = {acc[i][4] + bias1.x, acc[i][5] + bias1.y,
                     acc[i][6] + bias1.z, acc[i][7] + bias1.w};
        *(float4*)(op + tx4) = r0;
        *(float4*)(op + 64 + tx4) = r1;
    }
}

// ----------------------------------------------------------------------------
// Kernel 2: W[b,q,k] = adj * exp(Q.K), with fused row-sum accumulation.
// ----------------------------------------------------------------------------
__global__ __launch_bounds__(256, 2)
void score_kernel(const float* __restrict__ adj)
{
    const int b  = blockIdx.z;
    const int q0 = blockIdx.x * 128;
    const int c0 = blockIdx.y * 128;
    const float* Qm = g_Q + (size_t)b * NN * DD;
    const float* Km = g_K + (size_t)b * NN * DD;

    __shared__ float As[2][16][128];
    __shared__ float Bs[2][16][128];

    const int tid = threadIdx.x;
    const int tx  = tid & 15;
    const int tx4 = tx * 4;
    const int ty4 = (tid >> 4) * 4;
    const int rowL = tid & 127;
    const int cb = (tid >> 7) * 8;

    const float* Ag = Qm + (size_t)(q0 + rowL) * DD + cb;
    const float* Bg = Km + (size_t)(c0 + rowL) * DD + cb;

    float4 a0 = *(const float4*)(Ag);
    float4 a1 = *(const float4*)(Ag + 4);
    float4 b0 = *(const float4*)(Bg);
    float4 b1 = *(const float4*)(Bg + 4);
    XSTORE(As[0], a0, a1);
    XSTORE(Bs[0], b0, b1);
    __syncthreads();

    float acc[8][8];
    #pragma unroll
    for (int i = 0; i < 8; i++)
        #pragma unroll
        for (int j = 0; j < 8; j++) acc[i][j] = 0.f;

    int buf = 0;
    for (int k0 = 16; k0 < DD; k0 += 16) {
        a0 = *(const float4*)(Ag + k0);
        a1 = *(const float4*)(Ag + k0 + 4);
        b0 = *(const float4*)(Bg + k0);
        b1 = *(const float4*)(Bg + k0 + 4);
        COMPUTE_STAGE(As[buf], Bs[buf]);
        XSTORE(As[buf ^ 1], a0, a1);
        XSTORE(Bs[buf ^ 1], b0, b1);
        __syncthreads();
        buf ^= 1;
    }
    COMPUTE_STAGE(As[buf], Bs[buf]);

    // Epilogue: mask*exp, store W, accumulate row sums (fused rowsum pass).
    #pragma unroll
    for (int i = 0; i < 8; i++) {
        const int row = q0 + (i < 4 ? ty4 + i : 64 + ty4 + i - 4);
        const size_t base = ((size_t)b * NN + row) * NN + c0;
        float4 A0 = *(const float4*)(adj + base + tx4);
        float4 A1 = *(const float4*)(adj + base + 64 + tx4);
        float4 r0 = {A0.x * __expf(acc[i][0]), A0.y * __expf(acc[i][1]),
                     A0.z * __expf(acc[i][2]), A0.w * __expf(acc[i][3])};
        float4 r1 = {A1.x * __expf(acc[i][4]), A1.y * __expf(acc[i][5]),
                     A1.z * __expf(acc[i][6]), A1.w * __expf(acc[i][7])};
        *(float4*)(g_W + base + tx4) = r0;
        *(float4*)(g_W + base + 64 + tx4) = r1;

        float s = r0.x + r0.y + r0.z + r0.w + r1.x + r1.y + r1.z + r1.w;
        #pragma unroll
        for (int o = 1; o < 16; o <<= 1)
            s += __shfl_xor_sync(0xffffffffu, s, o);
        if (tx == 0)
            atomicAdd(&g_rs[b * NN + row], s);
    }
}

// ----------------------------------------------------------------------------
// Kernel 3: O = (W @ V) / rowsum.  A=W K-major [N,N], B=V row-major [N,D].
// ----------------------------------------------------------------------------
__global__ __launch_bounds__(256, 2)
void out_kernel(float* __restrict__ out)
{
    const int b  = blockIdx.z;
    const int m0 = blockIdx.x * 128;
    const int n0 = blockIdx.y * 128;
    const float* Am = g_W + (size_t)b * NN * NN;
    const float* Bv = g_V + (size_t)b * NN * DD;

    __shared__ float As[2][16][128];
    __shared__ float Bs[2][16][128];

    const int tid = threadIdx.x;
    const int tx4 = (tid & 15) * 4;
    const int ty4 = (tid >> 4) * 4;
    const int rowL = tid & 127;
    const int cb = (tid >> 7) * 8;
    const int kB = tid >> 5;          // 0..7
    const int c4 = (tid & 31) * 4;    // 0..124

    const float* Ag = Am + (size_t)(m0 + rowL) * NN + cb;
    const float* Bg = Bv + (size_t)kB * DD + n0 + c4;

    float4 a0 = *(const float4*)(Ag);
    float4 a1 = *(const float4*)(Ag + 4);
    float4 b0 = *(const float4*)(Bg);
    float4 b1 = *(const float4*)(Bg + (size_t)8 * DD);
    XSTORE(As[0], a0, a1);
    *(float4*)&Bs[0][kB][c4] = b0;
    *(float4*)&Bs[0][kB + 8][c4] = b1;
    __syncthreads();

    float acc[8][8];
    #pragma unroll
    for (int i = 0; i < 8; i++)
        #pragma unroll
        for (int j = 0; j < 8; j++) acc[i][j] = 0.f;

    int buf = 0;
    for (int k0 = 16; k0 < NN; k0 += 16) {
        a0 = *(const float4*)(Ag + k0);
        a1 = *(const float4*)(Ag + k0 + 4);
        b0 = *(const float4*)(Bg + (size_t)k0 * DD);
        b1 = *(const float4*)(Bg + (size_t)(k0 + 8) * DD);
        COMPUTE_STAGE(As[buf], Bs[buf]);
        XSTORE(As[buf ^ 1], a0, a1);
        *(float4*)&Bs[buf ^ 1][kB][c4] = b0;
        *(float4*)&Bs[buf ^ 1][kB + 8][c4] = b1;
        __syncthreads();
        buf ^= 1;
    }
    COMPUTE_STAGE(As[buf], Bs[buf]);

    #pragma unroll
    for (int i = 0; i < 8; i++) {
        const int row = m0 + (i < 4 ? ty4 + i : 64 + ty4 + i - 4);
        const float inv = 1.0f / g_rs[b * NN + row];
        float* op = out + ((size_t)b * NN + row) * DD + n0;
        float4 r0 = {acc[i][0] * inv, acc[i][1] * inv,
                     acc[i][2] * inv, acc[i][3] * inv};
        float4 r1 = {acc[i][4] * inv, acc[i][5] * inv,
                     acc[i][6] * inv, acc[i][7] * inv};
        *(float4*)(op + tx4) = r0;
        *(float4*)(op + 64 + tx4) = r1;
    }
}

// ----------------------------------------------------------------------------
extern "C" void kernel_launch(void* const* d_in, const int* in_sizes, int n_in,
                              void* d_out, int out_size)
{
    const float* x    = (const float*)d_in[0];
    const float* adj  = (const float*)d_in[1];
    const float* Wq_w = (const float*)d_in[2];
    const float* Wq_b = (const float*)d_in[3];
    const float* Wk_w = (const float*)d_in[4];
    const float* Wk_b = (const float*)d_in[5];
    const float* Wv_w = (const float*)d_in[6];
    const float* Wv_b = (const float*)d_in[7];
    float* out = (float*)d_out;

    zero_rs_kernel<<<(BB * NN) / 256, 256>>>();
    {
        dim3 grid(BB * NN / 128, DD / 128, 3);
        qkv_kernel<<<grid, 256>>>(x, Wq_w, Wq_b, Wk_w, Wk_b, Wv_w, Wv_b);
    }
    {
        dim3 grid(NN / 128, NN / 128, BB);
        score_kernel<<<grid, 256>>>(adj);
    }
    {
        dim3 grid(NN / 128, DD / 128, BB);
        out_kernel<<<grid, 256>>>(out);
    }
}

// round 4
// speedup vs baseline: 3.0364x; 2.5673x over previous
#include <cuda_runtime.h>
#include <cuda_bf16.h>
#include <cstdint>
#include <cstddef>

#define BB 8
#define NN 2048
#define DDIM 512

typedef __nv_bfloat16 bf16;

// ---------------------------------------------------------------------------
// Scratch (static device globals: allocation-free rule)
// ---------------------------------------------------------------------------
__device__ bf16 g_xh[(size_t)BB * NN * DDIM];
__device__ bf16 g_xl[(size_t)BB * NN * DDIM];
__device__ bf16 g_wqh[(size_t)DDIM * DDIM];
__device__ bf16 g_wql[(size_t)DDIM * DDIM];
__device__ bf16 g_wkh[(size_t)DDIM * DDIM];
__device__ bf16 g_wkl[(size_t)DDIM * DDIM];
__device__ bf16 g_wvh[(size_t)DDIM * DDIM];
__device__ bf16 g_wvl[(size_t)DDIM * DDIM];
__device__ bf16 g_Qh[(size_t)BB * NN * DDIM];
__device__ bf16 g_Ql[(size_t)BB * NN * DDIM];
__device__ bf16 g_Kh[(size_t)BB * NN * DDIM];
__device__ bf16 g_Kl[(size_t)BB * NN * DDIM];
__device__ bf16 g_Vh[(size_t)BB * NN * DDIM];
__device__ bf16 g_Vl[(size_t)BB * NN * DDIM];
__device__ bf16 g_Wmh[(size_t)BB * NN * NN];
__device__ bf16 g_Wml[(size_t)BB * NN * NN];
__device__ float g_rs[(size_t)BB * NN];

// ---------------------------------------------------------------------------
// Low-level helpers (all family-baseline PTX: cp.async / ldmatrix / mma.sync)
// ---------------------------------------------------------------------------
__device__ __forceinline__ uint32_t smem_to_u32(const void* p) {
    uint32_t a;
    asm("{ .reg .u64 t; cvta.to.shared.u64 t, %1; cvt.u32.u64 %0, t; }"
        : "=r"(a) : "l"(p));
    return a;
}

__device__ __forceinline__ void cp16(uint32_t dst, const void* src) {
    asm volatile("cp.async.cg.shared.global [%0], [%1], 16;"
                 :: "r"(dst), "l"(src));
}
__device__ __forceinline__ void cp_commit() {
    asm volatile("cp.async.commit_group;" ::: "memory");
}
__device__ __forceinline__ void cp_wait1() {
    asm volatile("cp.async.wait_group 1;" ::: "memory");
}
__device__ __forceinline__ void cp_wait0() {
    asm volatile("cp.async.wait_group 0;" ::: "memory");
}

__device__ __forceinline__ void ldsm4(uint32_t* r, uint32_t addr) {
    asm volatile("ldmatrix.sync.aligned.m8n8.x4.shared.b16 {%0,%1,%2,%3}, [%4];"
                 : "=r"(r[0]), "=r"(r[1]), "=r"(r[2]), "=r"(r[3]) : "r"(addr));
}
__device__ __forceinline__ void ldsm4t(uint32_t* r, uint32_t addr) {
    asm volatile("ldmatrix.sync.aligned.m8n8.x4.trans.shared.b16 {%0,%1,%2,%3}, [%4];"
                 : "=r"(r[0]), "=r"(r[1]), "=r"(r[2]), "=r"(r[3]) : "r"(addr));
}

__device__ __forceinline__ void mma16816(float* c, const uint32_t* a, const uint32_t* b) {
    asm volatile(
        "mma.sync.aligned.m16n8k16.row.col.f32.bf16.bf16.f32 "
        "{%0,%1,%2,%3}, {%4,%5,%6,%7}, {%8,%9}, {%0,%1,%2,%3};"
        : "+f"(c[0]), "+f"(c[1]), "+f"(c[2]), "+f"(c[3])
        : "r"(a[0]), "r"(a[1]), "r"(a[2]), "r"(a[3]), "r"(b[0]), "r"(b[1]));
}

__device__ __forceinline__ uint32_t pack_bf16(bf16 a, bf16 b) {
    return (uint32_t)__bfloat16_as_ushort(a) | ((uint32_t)__bfloat16_as_ushort(b) << 16);
}
__device__ __forceinline__ void split_val(float v, bf16& h, bf16& l) {
    h = __float2bfloat16(v);
    l = __float2bfloat16(v - __bfloat162float(h));
}

// ---------------------------------------------------------------------------
// SMEM geometry: 2 stages x 4 slabs x 16KB = 128KB
// K-major slab: 128 rows x 128B (64 bf16), XOR-swizzled 16B chunks.
// N-major slab (out-kernel B): 64 rows x 256B (128 bf16).
// ---------------------------------------------------------------------------
static constexpr int SLAB = 16384;
static constexpr int BUFSZ = 4 * SLAB;
static constexpr int SMEM_TOTAL = 2 * BUFSZ;

// Load one k-major slab stage: rows 0..127 of [row*ld + koff .. +64) bf16.
// 64 threads (u = 0..63): chunk = u&7, rows (u>>3) + 8p.
__device__ __forceinline__ void load_km(const bf16* src, size_t ld, uint32_t sbase, int u)
{
    const int chunk = u & 7;
    const int r0 = u >> 3;
    #pragma unroll
    for (int p = 0; p < 16; p++) {
        const int row = r0 + 8 * p;
        const uint32_t off = row * 128 + (((chunk ^ (row & 7))) << 4);
        cp16(sbase + off, src + (size_t)row * ld + chunk * 8);
    }
}

// Load one n-major slab stage: 64 rows x 128 cols (256B rows).
__device__ __forceinline__ void load_nm(const bf16* src, size_t ld, uint32_t sbase, int u)
{
    const int chunk = u & 15;
    const int r0 = u >> 4;
    #pragma unroll
    for (int p = 0; p < 16; p++) {
        const int row = r0 + 4 * p;
        const uint32_t off = row * 256 + (((chunk ^ (row & 7))) << 4);
        cp16(sbase + off, src + (size_t)row * ld + chunk * 8);
    }
}

// 3-pass split MMA over one 64-k chunk, B slab k-major (score/qkv kernels).
// Warp tile 64x32: wm0 = (wid&1)*64, wn0 = (wid>>1)*32.
__device__ __forceinline__ void compute_nt(
    uint32_t sAh, uint32_t sAl, uint32_t sBh, uint32_t sBl,
    float c[4][4][4], int lane, int wm0, int wn0)
{
    #pragma unroll
    for (int kk = 0; kk < 4; kk++) {
        uint32_t aH[4][4], aL[4][4];
        const int ar = lane & 15;
        const int ac = 2 * kk + (lane >> 4);
        #pragma unroll
        for (int i = 0; i < 4; i++) {
            const int row = wm0 + i * 16 + ar;
            const uint32_t off = row * 128 + ((ac ^ (row & 7)) << 4);
            ldsm4(aH[i], sAh + off);
            ldsm4(aL[i], sAl + off);
        }
        uint32_t bH[4][2], bL[4][2];
        const int br = (lane & 7) + ((lane >> 4) & 1) * 8;
        const int bc = 2 * kk + ((lane >> 3) & 1);
        #pragma unroll
        for (int jj = 0; jj < 2; jj++) {
            const int row = wn0 + jj * 16 + br;
            const uint32_t off = row * 128 + ((bc ^ (row & 7)) << 4);
            uint32_t t[4];
            ldsm4(t, sBh + off);
            bH[2 * jj][0] = t[0]; bH[2 * jj][1] = t[1];
            bH[2 * jj + 1][0] = t[2]; bH[2 * jj + 1][1] = t[3];
            ldsm4(t, sBl + off);
            bL[2 * jj][0] = t[0]; bL[2 * jj][1] = t[1];
            bL[2 * jj + 1][0] = t[2]; bL[2 * jj + 1][1] = t[3];
        }
        #pragma unroll
        for (int i = 0; i < 4; i++)
            #pragma unroll
            for (int j = 0; j < 4; j++) {
                mma16816(c[i][j], aH[i], bH[j]);
                mma16816(c[i][j], aH[i], bL[j]);
                mma16816(c[i][j], aL[i], bH[j]);
            }
    }
}

// Same but B slab n-major (64 k-rows x 128 n-cols), loaded with ldmatrix.trans.
__device__ __forceinline__ void compute_tr(
    uint32_t sAh, uint32_t sAl, uint32_t sBh, uint32_t sBl,
    float c[4][4][4], int lane, int wm0, int wn0)
{
    #pragma unroll
    for (int kk = 0; kk < 4; kk++) {
        uint32_t aH[4][4], aL[4][4];
        const int ar = lane & 15;
        const int ac = 2 * kk + (lane >> 4);
        #pragma unroll
        for (int i = 0; i < 4; i++) {
            const int row = wm0 + i * 16 + ar;
            const uint32_t off = row * 128 + ((ac ^ (row & 7)) << 4);
            ldsm4(aH[i], sAh + off);
            ldsm4(aL[i], sAl + off);
        }
        uint32_t bH[4][2], bL[4][2];
        const int br = kk * 16 + (lane & 7) + ((lane >> 3) & 1) * 8;
        #pragma unroll
        for (int jj = 0; jj < 2; jj++) {
            const int ch = (wn0 >> 3) + 2 * jj + (lane >> 4);
            const uint32_t off = br * 256 + ((ch ^ (br & 7)) << 4);
            uint32_t t[4];
            ldsm4t(t, sBh + off);
            bH[2 * jj][0] = t[0]; bH[2 * jj][1] = t[1];
            bH[2 * jj + 1][0] = t[2]; bH[2 * jj + 1][1] = t[3];
            ldsm4t(t, sBl + off);
            bL[2 * jj][0] = t[0]; bL[2 * jj][1] = t[1];
            bL[2 * jj + 1][0] = t[2]; bL[2 * jj + 1][1] = t[3];
        }
        #pragma unroll
        for (int i = 0; i < 4; i++)
            #pragma unroll
            for (int j = 0; j < 4; j++) {
                mma16816(c[i][j], aH[i], bH[j]);
                mma16816(c[i][j], aH[i], bL[j]);
                mma16816(c[i][j], aL[i], bH[j]);
            }
    }
}

// ---------------------------------------------------------------------------
// Kernel 1: QKV projections (A = x split, B = weights split, bias epilogue)
// ---------------------------------------------------------------------------
__global__ __launch_bounds__(256, 1)
void qkv_mma_kernel(const float* __restrict__ bq, const float* __restrict__ bk,
                    const float* __restrict__ bv)
{
    extern __shared__ char smem[];
    const uint32_t sb = smem_to_u32(smem);
    const int tid = threadIdx.x, wid = tid >> 5, lane = tid & 31;
    const int slab = tid >> 6, u = tid & 63;
    const int wm0 = (wid & 1) * 64, wn0 = (wid >> 1) * 32;

    const int m0 = blockIdx.x * 128, n0 = blockIdx.y * 128, z = blockIdx.z;
    const bf16 *Wh_, *Wl_;
    const float* bias;
    bf16 *Dh, *Dl;
    if (z == 0)      { Wh_ = g_wqh; Wl_ = g_wql; bias = bq; Dh = g_Qh; Dl = g_Ql; }
    else if (z == 1) { Wh_ = g_wkh; Wl_ = g_wkl; bias = bk; Dh = g_Kh; Dl = g_Kl; }
    else             { Wh_ = g_wvh; Wl_ = g_wvl; bias = bv; Dh = g_Vh; Dl = g_Vl; }

    const bf16* src;
    if (slab == 0)      src = g_xh + (size_t)m0 * DDIM;
    else if (slab == 1) src = g_xl + (size_t)m0 * DDIM;
    else if (slab == 2) src = Wh_ + (size_t)n0 * DDIM;
    else                src = Wl_ + (size_t)n0 * DDIM;

    const int NIT = DDIM / 64;
    load_km(src, DDIM, sb + slab * SLAB, u);
    cp_commit();

    float c[4][4][4];
    #pragma unroll
    for (int i = 0; i < 4; i++)
        #pragma unroll
        for (int j = 0; j < 4; j++)
            #pragma unroll
            for (int k = 0; k < 4; k++) c[i][j][k] = 0.f;

    for (int it = 0; it < NIT; it++) {
        if (it + 1 < NIT) {
            load_km(src + (size_t)(it + 1) * 64, DDIM,
                    sb + ((it + 1) & 1) * BUFSZ + slab * SLAB, u);
            cp_commit();
            cp_wait1();
        } else cp_wait0();
        __syncthreads();
        const uint32_t base = sb + (it & 1) * BUFSZ;
        compute_nt(base, base + SLAB, base + 2 * SLAB, base + 3 * SLAB,
                   c, lane, wm0, wn0);
        __syncthreads();
    }

    #pragma unroll
    for (int i = 0; i < 4; i++)
        #pragma unroll
        for (int h = 0; h < 2; h++) {
            const int m = m0 + wm0 + i * 16 + (lane >> 2) + 8 * h;
            #pragma unroll
            for (int j = 0; j < 4; j++) {
                const int col = n0 + wn0 + j * 8 + 2 * (lane & 3);
                const float2 bs = *(const float2*)(bias + col);
                const float v0 = c[i][j][2 * h] + bs.x;
                const float v1 = c[i][j][2 * h + 1] + bs.y;
                bf16 h0, h1, l0, l1;
                split_val(v0, h0, l0);
                split_val(v1, h1, l1);
                const size_t idx = (size_t)m * DDIM + col;
                *(uint32_t*)(Dh + idx) = pack_bf16(h0, h1);
                *(uint32_t*)(Dl + idx) = pack_bf16(l0, l1);
            }
        }
}

// ---------------------------------------------------------------------------
// Kernel 2: scores + mask*exp + split store W + fused rowsum atomics
// ---------------------------------------------------------------------------
__global__ __launch_bounds__(256, 1)
void score_mma_kernel(const float* __restrict__ adj)
{
    extern __shared__ char smem[];
    const uint32_t sb = smem_to_u32(smem);
    const int tid = threadIdx.x, wid = tid >> 5, lane = tid & 31;
    const int slab = tid >> 6, u = tid & 63;
    const int wm0 = (wid & 1) * 64, wn0 = (wid >> 1) * 32;

    const int q0 = blockIdx.x * 128, c0 = blockIdx.y * 128, b = blockIdx.z;

    const bf16* src;
    if (slab == 0)      src = g_Qh + ((size_t)b * NN + q0) * DDIM;
    else if (slab == 1) src = g_Ql + ((size_t)b * NN + q0) * DDIM;
    else if (slab == 2) src = g_Kh + ((size_t)b * NN + c0) * DDIM;
    else                src = g_Kl + ((size_t)b * NN + c0) * DDIM;

    const int NIT = DDIM / 64;
    load_km(src, DDIM, sb + slab * SLAB, u);
    cp_commit();

    float c[4][4][4];
    #pragma unroll
    for (int i = 0; i < 4; i++)
        #pragma unroll
        for (int j = 0; j < 4; j++)
            #pragma unroll
            for (int k = 0; k < 4; k++) c[i][j][k] = 0.f;

    for (int it = 0; it < NIT; it++) {
        if (it + 1 < NIT) {
            load_km(src + (size_t)(it + 1) * 64, DDIM,
                    sb + ((it + 1) & 1) * BUFSZ + slab * SLAB, u);
            cp_commit();
            cp_wait1();
        } else cp_wait0();
        __syncthreads();
        const uint32_t base = sb + (it & 1) * BUFSZ;
        compute_nt(base, base + SLAB, base + 2 * SLAB, base + 3 * SLAB,
                   c, lane, wm0, wn0);
        __syncthreads();
    }

    #pragma unroll
    for (int i = 0; i < 4; i++)
        #pragma unroll
        for (int h = 0; h < 2; h++) {
            const int r = q0 + wm0 + i * 16 + (lane >> 2) + 8 * h;
            const size_t rowbase = ((size_t)b * NN + r) * NN;
            float rsum = 0.f;
            #pragma unroll
            for (int j = 0; j < 4; j++) {
                const int cc = c0 + wn0 + j * 8 + 2 * (lane & 3);
                const float2 a2 = *(const float2*)(adj + rowbase + cc);
                const float w0 = a2.x * __expf(c[i][j][2 * h]);
                const float w1 = a2.y * __expf(c[i][j][2 * h + 1]);
                rsum += w0 + w1;
                bf16 h0, h1, l0, l1;
                split_val(w0, h0, l0);
                split_val(w1, h1, l1);
                *(uint32_t*)(g_Wmh + rowbase + cc) = pack_bf16(h0, h1);
                *(uint32_t*)(g_Wml + rowbase + cc) = pack_bf16(l0, l1);
            }
            rsum += __shfl_xor_sync(0xffffffffu, rsum, 1);
            rsum += __shfl_xor_sync(0xffffffffu, rsum, 2);
            if ((lane & 3) == 0)
                atomicAdd(&g_rs[b * NN + r], rsum);
        }
}

// ---------------------------------------------------------------------------
// Kernel 3: O = (W @ V) / rowsum   (B = V natural layout via ldmatrix.trans)
// ---------------------------------------------------------------------------
__global__ __launch_bounds__(256, 1)
void out_mma_kernel(float* __restrict__ out)
{
    extern __shared__ char smem[];
    const uint32_t sb = smem_to_u32(smem);
    const int tid = threadIdx.x, wid = tid >> 5, lane = tid & 31;
    const int slab = tid >> 6, u = tid & 63;
    const int wm0 = (wid & 1) * 64, wn0 = (wid >> 1) * 32;

    const int q0 = blockIdx.x * 128, n0 = blockIdx.y * 128, b = blockIdx.z;

    const bf16 *srcA, *srcB;
    if (slab == 0)      srcA = g_Wmh + ((size_t)b * NN + q0) * NN;
    else if (slab == 1) srcA = g_Wml + ((size_t)b * NN + q0) * NN;
    else if (slab == 2) srcB = g_Vh + (size_t)b * NN * DDIM + n0;
    else                srcB = g_Vl + (size_t)b * NN * DDIM + n0;

    const int NIT = NN / 64;
    if (slab < 2) load_km(srcA, NN, sb + slab * SLAB, u);
    else          load_nm(srcB, DDIM, sb + slab * SLAB, u);
    cp_commit();

    float c[4][4][4];
    #pragma unroll
    for (int i = 0; i < 4; i++)
        #pragma unroll
        for (int j = 0; j < 4; j++)
            #pragma unroll
            for (int k = 0; k < 4; k++) c[i][j][k] = 0.f;

    for (int it = 0; it < NIT; it++) {
        if (it + 1 < NIT) {
            const uint32_t dst = sb + ((it + 1) & 1) * BUFSZ + slab * SLAB;
            if (slab < 2) load_km(srcA + (size_t)(it + 1) * 64, NN, dst, u);
            else          load_nm(srcB + (size_t)(it + 1) * 64 * DDIM, DDIM, dst, u);
            cp_commit();
            cp_wait1();
        } else cp_wait0();
        __syncthreads();
        const uint32_t base = sb + (it & 1) * BUFSZ;
        compute_tr(base, base + SLAB, base + 2 * SLAB, base + 3 * SLAB,
                   c, lane, wm0, wn0);
        __syncthreads();
    }

    #pragma unroll
    for (int i = 0; i < 4; i++)
        #pragma unroll
        for (int h = 0; h < 2; h++) {
            const int r = q0 + wm0 + i * 16 + (lane >> 2) + 8 * h;
            const float inv = 1.0f / g_rs[b * NN + r];
            float* op = out + ((size_t)b * NN + r) * DDIM;
            #pragma unroll
            for (int j = 0; j < 4; j++) {
                const int col = n0 + wn0 + j * 8 + 2 * (lane & 3);
                float2 v;
                v.x = c[i][j][2 * h] * inv;
                v.y = c[i][j][2 * h + 1] * inv;
                *(float2*)(op + col) = v;
            }
        }
}

// ---------------------------------------------------------------------------
// Elementwise: fp32 -> (hi, lo) bf16 split;  rowsum zero
// ---------------------------------------------------------------------------
__global__ void split_kernel(const float* __restrict__ src,
                             bf16* __restrict__ h, bf16* __restrict__ l, int n4)
{
    int i = blockIdx.x * blockDim.x + threadIdx.x;
    if (i >= n4) return;
    float4 v = ((const float4*)src)[i];
    bf16 h0, h1, h2, h3, l0, l1, l2, l3;
    split_val(v.x, h0, l0); split_val(v.y, h1, l1);
    split_val(v.z, h2, l2); split_val(v.w, h3, l3);
    ((uint2*)h)[i] = make_uint2(pack_bf16(h0, h1), pack_bf16(h2, h3));
    ((uint2*)l)[i] = make_uint2(pack_bf16(l0, l1), pack_bf16(l2, l3));
}

__global__ void zero_rs_kernel() {
    g_rs[blockIdx.x * 256 + threadIdx.x] = 0.f;
}

// ---------------------------------------------------------------------------
extern "C" void kernel_launch(void* const* d_in, const int* in_sizes, int n_in,
                              void* d_out, int out_size)
{
    const float* x    = (const float*)d_in[0];
    const float* adj  = (const float*)d_in[1];
    const float* Wq_w = (const float*)d_in[2];
    const float* Wq_b = (const float*)d_in[3];
    const float* Wk_w = (const float*)d_in[4];
    const float* Wk_b = (const float*)d_in[5];
    const float* Wv_w = (const float*)d_in[6];
    const float* Wv_b = (const float*)d_in[7];
    float* out = (float*)d_out;

    cudaFuncSetAttribute(qkv_mma_kernel, cudaFuncAttributeMaxDynamicSharedMemorySize, SMEM_TOTAL);
    cudaFuncSetAttribute(score_mma_kernel, cudaFuncAttributeMaxDynamicSharedMemorySize, SMEM_TOTAL);
    cudaFuncSetAttribute(out_mma_kernel, cudaFuncAttributeMaxDynamicSharedMemorySize, SMEM_TOTAL);

    bf16 *xh, *xl, *wqh, *wql, *wkh, *wkl, *wvh, *wvl;
    cudaGetSymbolAddress((void**)&xh, g_xh);   cudaGetSymbolAddress((void**)&xl, g_xl);
    cudaGetSymbolAddress((void**)&wqh, g_wqh); cudaGetSymbolAddress((void**)&wql, g_wql);
    cudaGetSymbolAddress((void**)&wkh, g_wkh); cudaGetSymbolAddress((void**)&wkl, g_wkl);
    cudaGetSymbolAddress((void**)&wvh, g_wvh); cudaGetSymbolAddress((void**)&wvl, g_wvl);

    {
        int n4 = BB * NN * DDIM / 4;
        split_kernel<<<(n4 + 255) / 256, 256>>>(x, xh, xl, n4);
        int w4 = DDIM * DDIM / 4;
        split_kernel<<<(w4 + 255) / 256, 256>>>(Wq_w, wqh, wql, w4);
        split_kernel<<<(w4 + 255) / 256, 256>>>(Wk_w, wkh, wkl, w4);
        split_kernel<<<(w4 + 255) / 256, 256>>>(Wv_w, wvh, wvl, w4);
    }
    zero_rs_kernel<<<(BB * NN) / 256, 256>>>();

    {
        dim3 grid(BB * NN / 128, DDIM / 128, 3);
        qkv_mma_kernel<<<grid, 256, SMEM_TOTAL>>>(Wq_b, Wk_b, Wv_b);
    }
    {
        dim3 grid(NN / 128, NN / 128, BB);
        score_mma_kernel<<<grid, 256, SMEM_TOTAL>>>(adj);
    }
    {
        dim3 grid(NN / 128, DDIM / 128, BB);
        out_mma_kernel<<<grid, 256, SMEM_TOTAL>>>(out);
    }
}

// round 5
// speedup vs baseline: 3.0872x; 1.0167x over previous
#include <cuda_runtime.h>
#include <cuda_bf16.h>
#include <cstdint>
#include <cstddef>

#define BB 8
#define NN 2048
#define DDIM 512

typedef __nv_bfloat16 bf16;

// ---------------------------------------------------------------------------
// Scratch (static device globals: allocation-free rule)
// ---------------------------------------------------------------------------
__device__ bf16 g_xh[(size_t)BB * NN * DDIM];
__device__ bf16 g_xl[(size_t)BB * NN * DDIM];
__device__ bf16 g_wqh[(size_t)DDIM * DDIM];
__device__ bf16 g_wql[(size_t)DDIM * DDIM];
__device__ bf16 g_wkh[(size_t)DDIM * DDIM];
__device__ bf16 g_wkl[(size_t)DDIM * DDIM];
__device__ bf16 g_wvh[(size_t)DDIM * DDIM];
__device__ bf16 g_wvl[(size_t)DDIM * DDIM];
__device__ bf16 g_Qh[(size_t)BB * NN * DDIM];
__device__ bf16 g_Ql[(size_t)BB * NN * DDIM];
__device__ bf16 g_Kh[(size_t)BB * NN * DDIM];
__device__ bf16 g_Kl[(size_t)BB * NN * DDIM];
__device__ bf16 g_Vh[(size_t)BB * NN * DDIM];
__device__ bf16 g_Vl[(size_t)BB * NN * DDIM];
__device__ bf16 g_Wmh[(size_t)BB * NN * NN];
__device__ bf16 g_Wml[(size_t)BB * NN * NN];
__device__ float g_rs[(size_t)BB * NN];

// ---------------------------------------------------------------------------
// Low-level helpers (family-baseline PTX only: cp.async / ldmatrix / mma.sync)
// ---------------------------------------------------------------------------
__device__ __forceinline__ uint32_t smem_to_u32(const void* p) {
    uint32_t a;
    asm("{ .reg .u64 t; cvta.to.shared.u64 t, %1; cvt.u32.u64 %0, t; }"
        : "=r"(a) : "l"(p));
    return a;
}
__device__ __forceinline__ void cp16(uint32_t dst, const void* src) {
    asm volatile("cp.async.cg.shared.global [%0], [%1], 16;" :: "r"(dst), "l"(src));
}
__device__ __forceinline__ void cp_commit() {
    asm volatile("cp.async.commit_group;" ::: "memory");
}
__device__ __forceinline__ void cp_wait1() {
    asm volatile("cp.async.wait_group 1;" ::: "memory");
}
__device__ __forceinline__ void cp_wait0() {
    asm volatile("cp.async.wait_group 0;" ::: "memory");
}
__device__ __forceinline__ void ldsm4(uint32_t* r, uint32_t addr) {
    asm volatile("ldmatrix.sync.aligned.m8n8.x4.shared.b16 {%0,%1,%2,%3}, [%4];"
                 : "=r"(r[0]), "=r"(r[1]), "=r"(r[2]), "=r"(r[3]) : "r"(addr));
}
__device__ __forceinline__ void ldsm4t(uint32_t* r, uint32_t addr) {
    asm volatile("ldmatrix.sync.aligned.m8n8.x4.trans.shared.b16 {%0,%1,%2,%3}, [%4];"
                 : "=r"(r[0]), "=r"(r[1]), "=r"(r[2]), "=r"(r[3]) : "r"(addr));
}
__device__ __forceinline__ void mma16816(float* c, const uint32_t* a, const uint32_t* b) {
    asm volatile(
        "mma.sync.aligned.m16n8k16.row.col.f32.bf16.bf16.f32 "
        "{%0,%1,%2,%3}, {%4,%5,%6,%7}, {%8,%9}, {%0,%1,%2,%3};"
        : "+f"(c[0]), "+f"(c[1]), "+f"(c[2]), "+f"(c[3])
        : "r"(a[0]), "r"(a[1]), "r"(a[2]), "r"(a[3]), "r"(b[0]), "r"(b[1]));
}
__device__ __forceinline__ uint32_t pack_bf16(bf16 a, bf16 b) {
    return (uint32_t)__bfloat16_as_ushort(a) | ((uint32_t)__bfloat16_as_ushort(b) << 16);
}
__device__ __forceinline__ void split_val(float v, bf16& h, bf16& l) {
    h = __float2bfloat16(v);
    l = __float2bfloat16(v - __bfloat162float(h));
}

// ---------------------------------------------------------------------------
// SMEM: 2 stages x (Ah 32K | Al 32K | Bh 16K | Bl 16K) = 192 KB
// A slab: 256 rows x 128B (64 bf16, k-major).  B k-major: 128 rows x 128B.
// B n-major (out kernel V): 64 k-rows x 256B (128 bf16 cols).
// ---------------------------------------------------------------------------
static constexpr int ASLAB = 32768;
static constexpr int BSLAB = 16384;
static constexpr int STAGE = 2 * ASLAB + 2 * BSLAB;   // 98304
static constexpr int SMEM_TOTAL = 2 * STAGE;          // 196608

// A slab loader: 256x64 bf16 (ld in elements); 8 cp16 per thread.
__device__ __forceinline__ void load_A(const bf16* src, size_t ld, uint32_t sbase, int t)
{
    const int col = t & 7, r0 = t >> 3;
    #pragma unroll
    for (int p = 0; p < 8; p++) {
        const int row = r0 + 32 * p;
        const uint32_t off = row * 128 + ((col ^ (row & 7)) << 4);
        cp16(sbase + off, src + (size_t)row * ld + col * 8);
    }
}
// B k-major loader: 128x64 bf16; 4 cp16 per thread.
__device__ __forceinline__ void load_Bk(const bf16* src, size_t ld, uint32_t sbase, int t)
{
    const int col = t & 7, r0 = t >> 3;
    #pragma unroll
    for (int p = 0; p < 4; p++) {
        const int row = r0 + 32 * p;
        const uint32_t off = row * 128 + ((col ^ (row & 7)) << 4);
        cp16(sbase + off, src + (size_t)row * ld + col * 8);
    }
}
// B n-major loader: 64 k-rows x 128 n-cols; 4 cp16 per thread.
__device__ __forceinline__ void load_Bn(const bf16* src, size_t ld, uint32_t sbase, int t)
{
    const int col = t & 15, r0 = t >> 4;
    #pragma unroll
    for (int p = 0; p < 4; p++) {
        const int row = r0 + 16 * p;
        const uint32_t off = row * 256 + ((col ^ (row & 7)) << 4);
        cp16(sbase + off, src + (size_t)row * ld + col * 8);
    }
}

// 3-product split MMA over one 64-k chunk; warp tile 64x64 (4 m-frags, 8 n-frags).
// B slab k-major.
__device__ __forceinline__ void compute_nt(uint32_t base, float c[4][8][4],
                                           int lane, int wm0, int wn0)
{
    const uint32_t sAh = base, sAl = base + ASLAB;
    const uint32_t sBh = base + 2 * ASLAB, sBl = sBh + BSLAB;
    #pragma unroll
    for (int kk = 0; kk < 4; kk++) {
        uint32_t aH[4][4], aL[4][4];
        const int ar = lane & 15;
        const int ac = 2 * kk + (lane >> 4);
        #pragma unroll
        for (int i = 0; i < 4; i++) {
            const int row = wm0 + i * 16 + ar;
            const uint32_t off = row * 128 + ((ac ^ (row & 7)) << 4);
            ldsm4(aH[i], sAh + off);
            ldsm4(aL[i], sAl + off);
        }
        const int br = (lane & 7) + ((lane >> 4) & 1) * 8;
        const int bc = 2 * kk + ((lane >> 3) & 1);
        #pragma unroll
        for (int jj = 0; jj < 4; jj++) {
            const int row = wn0 + jj * 16 + br;
            const uint32_t off = row * 128 + ((bc ^ (row & 7)) << 4);
            uint32_t tH[4], tL[4];
            ldsm4(tH, sBh + off);
            ldsm4(tL, sBl + off);
            uint32_t b0H[2] = {tH[0], tH[1]}, b1H[2] = {tH[2], tH[3]};
            uint32_t b0L[2] = {tL[0], tL[1]}, b1L[2] = {tL[2], tL[3]};
            #pragma unroll
            for (int i = 0; i < 4; i++) {
                mma16816(c[i][2 * jj], aH[i], b0H);
                mma16816(c[i][2 * jj], aH[i], b0L);
                mma16816(c[i][2 * jj], aL[i], b0H);
                mma16816(c[i][2 * jj + 1], aH[i], b1H);
                mma16816(c[i][2 * jj + 1], aH[i], b1L);
                mma16816(c[i][2 * jj + 1], aL[i], b1H);
            }
        }
    }
}

// Same, B slab n-major via ldmatrix.trans.
__device__ __forceinline__ void compute_tr(uint32_t base, float c[4][8][4],
                                           int lane, int wm0, int wn0)
{
    const uint32_t sAh = base, sAl = base + ASLAB;
    const uint32_t sBh = base + 2 * ASLAB, sBl = sBh + BSLAB;
    #pragma unroll
    for (int kk = 0; kk < 4; kk++) {
        uint32_t aH[4][4], aL[4][4];
        const int ar = lane & 15;
        const int ac = 2 * kk + (lane >> 4);
        #pragma unroll
        for (int i = 0; i < 4; i++) {
            const int row = wm0 + i * 16 + ar;
            const uint32_t off = row * 128 + ((ac ^ (row & 7)) << 4);
            ldsm4(aH[i], sAh + off);
            ldsm4(aL[i], sAl + off);
        }
        const int br = kk * 16 + (lane & 7) + ((lane >> 3) & 1) * 8;
        #pragma unroll
        for (int jj = 0; jj < 4; jj++) {
            const int ch = (wn0 >> 3) + 2 * jj + (lane >> 4);
            const uint32_t off = br * 256 + ((ch ^ (br & 7)) << 4);
            uint32_t tH[4], tL[4];
            ldsm4t(tH, sBh + off);
            ldsm4t(tL, sBl + off);
            uint32_t b0H[2] = {tH[0], tH[1]}, b1H[2] = {tH[2], tH[3]};
            uint32_t b0L[2] = {tL[0], tL[1]}, b1L[2] = {tL[2], tL[3]};
            #pragma unroll
            for (int i = 0; i < 4; i++) {
                mma16816(c[i][2 * jj], aH[i], b0H);
                mma16816(c[i][2 * jj], aH[i], b0L);
                mma16816(c[i][2 * jj], aL[i], b0H);
                mma16816(c[i][2 * jj + 1], aH[i], b1H);
                mma16816(c[i][2 * jj + 1], aH[i], b1L);
                mma16816(c[i][2 * jj + 1], aL[i], b1H);
            }
        }
    }
}

#define ZERO_ACC(c)                                  \
    _Pragma("unroll")                                \
    for (int i = 0; i < 4; i++)                      \
        _Pragma("unroll")                            \
        for (int j = 0; j < 8; j++)                  \
            _Pragma("unroll")                        \
            for (int k = 0; k < 4; k++) c[i][j][k] = 0.f;

// ---------------------------------------------------------------------------
// Kernel 1: QKV projections. CTA tile 256(m) x 128(n).
// grid(x=n 4, y=m 64, z=matrix 3)
// ---------------------------------------------------------------------------
__global__ __launch_bounds__(256, 1)
void qkv_mma_kernel(const float* __restrict__ bq, const float* __restrict__ bk,
                    const float* __restrict__ bv)
{
    extern __shared__ char smem[];
    const uint32_t sb = smem_to_u32(smem);
    const int tid = threadIdx.x, wid = tid >> 5, lane = tid & 31;
    const int wm0 = (wid & 3) * 64, wn0 = (wid >> 2) * 64;

    const int n0 = blockIdx.x * 128, m0 = blockIdx.y * 256, z = blockIdx.z;
    const bf16 *Wh_, *Wl_;
    const float* bias;
    bf16 *Dh, *Dl;
    if (z == 0)      { Wh_ = g_wqh; Wl_ = g_wql; bias = bq; Dh = g_Qh; Dl = g_Ql; }
    else if (z == 1) { Wh_ = g_wkh; Wl_ = g_wkl; bias = bk; Dh = g_Kh; Dl = g_Kl; }
    else             { Wh_ = g_wvh; Wl_ = g_wvl; bias = bv; Dh = g_Vh; Dl = g_Vl; }

    const bf16* Ah = g_xh + (size_t)m0 * DDIM;
    const bf16* Al = g_xl + (size_t)m0 * DDIM;
    const bf16* Bh = Wh_ + (size_t)n0 * DDIM;
    const bf16* Bl = Wl_ + (size_t)n0 * DDIM;

    const int NIT = DDIM / 64;
    load_A(Ah, DDIM, sb, tid);
    load_A(Al, DDIM, sb + ASLAB, tid);
    load_Bk(Bh, DDIM, sb + 2 * ASLAB, tid);
    load_Bk(Bl, DDIM, sb + 2 * ASLAB + BSLAB, tid);
    cp_commit();

    float c[4][8][4];
    ZERO_ACC(c);

    for (int it = 0; it < NIT; it++) {
        if (it + 1 < NIT) {
            const uint32_t d = sb + ((it + 1) & 1) * STAGE;
            const size_t ko = (size_t)(it + 1) * 64;
            load_A(Ah + ko, DDIM, d, tid);
            load_A(Al + ko, DDIM, d + ASLAB, tid);
            load_Bk(Bh + ko, DDIM, d + 2 * ASLAB, tid);
            load_Bk(Bl + ko, DDIM, d + 2 * ASLAB + BSLAB, tid);
            cp_commit();
            cp_wait1();
        } else cp_wait0();
        __syncthreads();
        compute_nt(sb + (it & 1) * STAGE, c, lane, wm0, wn0);
        __syncthreads();
    }

    #pragma unroll
    for (int i = 0; i < 4; i++)
        #pragma unroll
        for (int h = 0; h < 2; h++) {
            const int m = m0 + wm0 + i * 16 + (lane >> 2) + 8 * h;
            #pragma unroll
            for (int j = 0; j < 8; j++) {
                const int col = n0 + wn0 + j * 8 + 2 * (lane & 3);
                const float2 bs = *(const float2*)(bias + col);
                const float v0 = c[i][j][2 * h] + bs.x;
                const float v1 = c[i][j][2 * h + 1] + bs.y;
                bf16 h0, h1, l0, l1;
                split_val(v0, h0, l0);
                split_val(v1, h1, l1);
                const size_t idx = (size_t)m * DDIM + col;
                *(uint32_t*)(Dh + idx) = pack_bf16(h0, h1);
                *(uint32_t*)(Dl + idx) = pack_bf16(l0, l1);
            }
        }
}

// ---------------------------------------------------------------------------
// Kernel 2: scores + mask*exp + split store W + fused rowsum atomics.
// CTA tile 256(q) x 128(c).  grid(x=c 16, y=q 8, z=b)
// ---------------------------------------------------------------------------
__global__ __launch_bounds__(256, 1)
void score_mma_kernel(const float* __restrict__ adj)
{
    extern __shared__ char smem[];
    const uint32_t sb = smem_to_u32(smem);
    const int tid = threadIdx.x, wid = tid >> 5, lane = tid & 31;
    const int wm0 = (wid & 3) * 64, wn0 = (wid >> 2) * 64;

    const int c0 = blockIdx.x * 128, q0 = blockIdx.y * 256, b = blockIdx.z;

    const bf16* Ah = g_Qh + ((size_t)b * NN + q0) * DDIM;
    const bf16* Al = g_Ql + ((size_t)b * NN + q0) * DDIM;
    const bf16* Bh = g_Kh + ((size_t)b * NN + c0) * DDIM;
    const bf16* Bl = g_Kl + ((size_t)b * NN + c0) * DDIM;

    const int NIT = DDIM / 64;
    load_A(Ah, DDIM, sb, tid);
    load_A(Al, DDIM, sb + ASLAB, tid);
    load_Bk(Bh, DDIM, sb + 2 * ASLAB, tid);
    load_Bk(Bl, DDIM, sb + 2 * ASLAB + BSLAB, tid);
    cp_commit();

    float c[4][8][4];
    ZERO_ACC(c);

    for (int it = 0; it < NIT; it++) {
        if (it + 1 < NIT) {
            const uint32_t d = sb + ((it + 1) & 1) * STAGE;
            const size_t ko = (size_t)(it + 1) * 64;
            load_A(Ah + ko, DDIM, d, tid);
            load_A(Al + ko, DDIM, d + ASLAB, tid);
            load_Bk(Bh + ko, DDIM, d + 2 * ASLAB, tid);
            load_Bk(Bl + ko, DDIM, d + 2 * ASLAB + BSLAB, tid);
            cp_commit();
            cp_wait1();
        } else cp_wait0();
        __syncthreads();
        compute_nt(sb + (it & 1) * STAGE, c, lane, wm0, wn0);
        __syncthreads();
    }

    #pragma unroll
    for (int i = 0; i < 4; i++)
        #pragma unroll
        for (int h = 0; h < 2; h++) {
            const int r = q0 + wm0 + i * 16 + (lane >> 2) + 8 * h;
            const size_t rowbase = ((size_t)b * NN + r) * NN;
            float rsum = 0.f;
            #pragma unroll
            for (int j = 0; j < 8; j++) {
                const int cc = c0 + wn0 + j * 8 + 2 * (lane & 3);
                const float2 a2 = *(const float2*)(adj + rowbase + cc);
                const float w0 = a2.x * __expf(c[i][j][2 * h]);
                const float w1 = a2.y * __expf(c[i][j][2 * h + 1]);
                rsum += w0 + w1;
                bf16 h0, h1, l0, l1;
                split_val(w0, h0, l0);
                split_val(w1, h1, l1);
                *(uint32_t*)(g_Wmh + rowbase + cc) = pack_bf16(h0, h1);
                *(uint32_t*)(g_Wml + rowbase + cc) = pack_bf16(l0, l1);
            }
            rsum += __shfl_xor_sync(0xffffffffu, rsum, 1);
            rsum += __shfl_xor_sync(0xffffffffu, rsum, 2);
            if ((lane & 3) == 0)
                atomicAdd(&g_rs[b * NN + r], rsum);
        }
}

// ---------------------------------------------------------------------------
// Kernel 3: O = (W @ V) / rowsum.  CTA tile 256(q) x 128(n).
// grid(x=n 4, y=q 8, z=b) — consecutive CTAs share W rows (L2 reuse).
// ---------------------------------------------------------------------------
__global__ __launch_bounds__(256, 1)
void out_mma_kernel(float* __restrict__ out)
{
    extern __shared__ char smem[];
    const uint32_t sb = smem_to_u32(smem);
    const int tid = threadIdx.x, wid = tid >> 5, lane = tid & 31;
    const int wm0 = (wid & 3) * 64, wn0 = (wid >> 2) * 64;

    const int n0 = blockIdx.x * 128, q0 = blockIdx.y * 256, b = blockIdx.z;

    const bf16* Ah = g_Wmh + ((size_t)b * NN + q0) * NN;
    const bf16* Al = g_Wml + ((size_t)b * NN + q0) * NN;
    const bf16* Bh = g_Vh + (size_t)b * NN * DDIM + n0;
    const bf16* Bl = g_Vl + (size_t)b * NN * DDIM + n0;

    const int NIT = NN / 64;
    load_A(Ah, NN, sb, tid);
    load_A(Al, NN, sb + ASLAB, tid);
    load_Bn(Bh, DDIM, sb + 2 * ASLAB, tid);
    load_Bn(Bl, DDIM, sb + 2 * ASLAB + BSLAB, tid);
    cp_commit();

    float c[4][8][4];
    ZERO_ACC(c);

    for (int it = 0; it < NIT; it++) {
        if (it + 1 < NIT) {
            const uint32_t d = sb + ((it + 1) & 1) * STAGE;
            const size_t ko = (size_t)(it + 1) * 64;
            load_A(Ah + ko, NN, d, tid);
            load_A(Al + ko, NN, d + ASLAB, tid);
            load_Bn(Bh + ko * DDIM, DDIM, d + 2 * ASLAB, tid);
            load_Bn(Bl + ko * DDIM, DDIM, d + 2 * ASLAB + BSLAB, tid);
            cp_commit();
            cp_wait1();
        } else cp_wait0();
        __syncthreads();
        compute_tr(sb + (it & 1) * STAGE, c, lane, wm0, wn0);
        __syncthreads();
    }

    #pragma unroll
    for (int i = 0; i < 4; i++)
        #pragma unroll
        for (int h = 0; h < 2; h++) {
            const int r = q0 + wm0 + i * 16 + (lane >> 2) + 8 * h;
            const float inv = 1.0f / g_rs[b * NN + r];
            float* op = out + ((size_t)b * NN + r) * DDIM;
            #pragma unroll
            for (int j = 0; j < 8; j++) {
                const int col = n0 + wn0 + j * 8 + 2 * (lane & 3);
                float2 v;
                v.x = c[i][j][2 * h] * inv;
                v.y = c[i][j][2 * h + 1] * inv;
                *(float2*)(op + col) = v;
            }
        }
}

// ---------------------------------------------------------------------------
// Elementwise: fp32 -> (hi, lo) bf16 split;  rowsum zero
// ---------------------------------------------------------------------------
__global__ void split_kernel(const float* __restrict__ src,
                             bf16* __restrict__ h, bf16* __restrict__ l, int n4)
{
    int i = blockIdx.x * blockDim.x + threadIdx.x;
    if (i >= n4) return;
    float4 v = ((const float4*)src)[i];
    bf16 h0, h1, h2, h3, l0, l1, l2, l3;
    split_val(v.x, h0, l0); split_val(v.y, h1, l1);
    split_val(v.z, h2, l2); split_val(v.w, h3, l3);
    ((uint2*)h)[i] = make_uint2(pack_bf16(h0, h1), pack_bf16(h2, h3));
    ((uint2*)l)[i] = make_uint2(pack_bf16(l0, l1), pack_bf16(l2, l3));
}

__global__ void zero_rs_kernel() {
    g_rs[blockIdx.x * 256 + threadIdx.x] = 0.f;
}

// ---------------------------------------------------------------------------
extern "C" void kernel_launch(void* const* d_in, const int* in_sizes, int n_in,
                              void* d_out, int out_size)
{
    const float* x    = (const float*)d_in[0];
    const float* adj  = (const float*)d_in[1];
    const float* Wq_w = (const float*)d_in[2];
    const float* Wq_b = (const float*)d_in[3];
    const float* Wk_w = (const float*)d_in[4];
    const float* Wk_b = (const float*)d_in[5];
    const float* Wv_w = (const float*)d_in[6];
    const float* Wv_b = (const float*)d_in[7];
    float* out = (float*)d_out;

    cudaFuncSetAttribute(qkv_mma_kernel, cudaFuncAttributeMaxDynamicSharedMemorySize, SMEM_TOTAL);
    cudaFuncSetAttribute(score_mma_kernel, cudaFuncAttributeMaxDynamicSharedMemorySize, SMEM_TOTAL);
    cudaFuncSetAttribute(out_mma_kernel, cudaFuncAttributeMaxDynamicSharedMemorySize, SMEM_TOTAL);

    bf16 *xh, *xl, *wqh, *wql, *wkh, *wkl, *wvh, *wvl;
    cudaGetSymbolAddress((void**)&xh, g_xh);   cudaGetSymbolAddress((void**)&xl, g_xl);
    cudaGetSymbolAddress((void**)&wqh, g_wqh); cudaGetSymbolAddress((void**)&wql, g_wql);
    cudaGetSymbolAddress((void**)&wkh, g_wkh); cudaGetSymbolAddress((void**)&wkl, g_wkl);
    cudaGetSymbolAddress((void**)&wvh, g_wvh); cudaGetSymbolAddress((void**)&wvl, g_wvl);

    {
        int n4 = BB * NN * DDIM / 4;
        split_kernel<<<(n4 + 255) / 256, 256>>>(x, xh, xl, n4);
        int w4 = DDIM * DDIM / 4;
        split_kernel<<<(w4 + 255) / 256, 256>>>(Wq_w, wqh, wql, w4);
        split_kernel<<<(w4 + 255) / 256, 256>>>(Wk_w, wkh, wkl, w4);
        split_kernel<<<(w4 + 255) / 256, 256>>>(Wv_w, wvh, wvl, w4);
    }
    zero_rs_kernel<<<(BB * NN) / 256, 256>>>();

    {
        dim3 grid(DDIM / 128, BB * NN / 256, 3);
        qkv_mma_kernel<<<grid, 256, SMEM_TOTAL>>>(Wq_b, Wk_b, Wv_b);
    }
    {
        dim3 grid(NN / 128, NN / 256, BB);
        score_mma_kernel<<<grid, 256, SMEM_TOTAL>>>(adj);
    }
    {
        dim3 grid(DDIM / 128, NN / 256, BB);
        out_mma_kernel<<<grid, 256, SMEM_TOTAL>>>(out);
    }
}

// round 6
// speedup vs baseline: 3.1281x; 1.0132x over previous
#include <cuda_runtime.h>
#include <cuda_bf16.h>
#include <cstdint>
#include <cstddef>

#define BB 8
#define NN 2048
#define DDIM 512

typedef __nv_bfloat16 bf16;

// ---------------------------------------------------------------------------
// Scratch (static device globals: allocation-free rule)
// ---------------------------------------------------------------------------
__device__ bf16 g_xh[(size_t)BB * NN * DDIM];
__device__ bf16 g_xl[(size_t)BB * NN * DDIM];
__device__ bf16 g_wqh[(size_t)DDIM * DDIM];
__device__ bf16 g_wql[(size_t)DDIM * DDIM];
__device__ bf16 g_wkh[(size_t)DDIM * DDIM];
__device__ bf16 g_wkl[(size_t)DDIM * DDIM];
__device__ bf16 g_wvh[(size_t)DDIM * DDIM];
__device__ bf16 g_wvl[(size_t)DDIM * DDIM];
__device__ bf16 g_Qh[(size_t)BB * NN * DDIM];
__device__ bf16 g_Ql[(size_t)BB * NN * DDIM];
__device__ bf16 g_Kh[(size_t)BB * NN * DDIM];
__device__ bf16 g_Kl[(size_t)BB * NN * DDIM];
__device__ bf16 g_Vh[(size_t)BB * NN * DDIM];
__device__ bf16 g_Vl[(size_t)BB * NN * DDIM];
__device__ bf16 g_Wmh[(size_t)BB * NN * NN];
__device__ bf16 g_Wml[(size_t)BB * NN * NN];
__device__ float g_rs[(size_t)BB * NN];

// ---------------------------------------------------------------------------
// Low-level helpers (family-baseline PTX only: cp.async / ldmatrix / mma.sync)
// ---------------------------------------------------------------------------
__device__ __forceinline__ uint32_t smem_to_u32(const void* p) {
    uint32_t a;
    asm("{ .reg .u64 t; cvta.to.shared.u64 t, %1; cvt.u32.u64 %0, t; }"
        : "=r"(a) : "l"(p));
    return a;
}
__device__ __forceinline__ void cp16(uint32_t dst, const void* src) {
    asm volatile("cp.async.cg.shared.global [%0], [%1], 16;" :: "r"(dst), "l"(src));
}
__device__ __forceinline__ void cp_commit() {
    asm volatile("cp.async.commit_group;" ::: "memory");
}
__device__ __forceinline__ void cp_wait1() {
    asm volatile("cp.async.wait_group 1;" ::: "memory");
}
__device__ __forceinline__ void cp_wait0() {
    asm volatile("cp.async.wait_group 0;" ::: "memory");
}
__device__ __forceinline__ void ldsm4(uint32_t* r, uint32_t addr) {
    asm volatile("ldmatrix.sync.aligned.m8n8.x4.shared.b16 {%0,%1,%2,%3}, [%4];"
                 : "=r"(r[0]), "=r"(r[1]), "=r"(r[2]), "=r"(r[3]) : "r"(addr));
}
__device__ __forceinline__ void ldsm4t(uint32_t* r, uint32_t addr) {
    asm volatile("ldmatrix.sync.aligned.m8n8.x4.trans.shared.b16 {%0,%1,%2,%3}, [%4];"
                 : "=r"(r[0]), "=r"(r[1]), "=r"(r[2]), "=r"(r[3]) : "r"(addr));
}
__device__ __forceinline__ void mma16816(float* c, const uint32_t* a, const uint32_t* b) {
    asm volatile(
        "mma.sync.aligned.m16n8k16.row.col.f32.bf16.bf16.f32 "
        "{%0,%1,%2,%3}, {%4,%5,%6,%7}, {%8,%9}, {%0,%1,%2,%3};"
        : "+f"(c[0]), "+f"(c[1]), "+f"(c[2]), "+f"(c[3])
        : "r"(a[0]), "r"(a[1]), "r"(a[2]), "r"(a[3]), "r"(b[0]), "r"(b[1]));
}
__device__ __forceinline__ uint32_t pack_bf16(bf16 a, bf16 b) {
    return (uint32_t)__bfloat16_as_ushort(a) | ((uint32_t)__bfloat16_as_ushort(b) << 16);
}
__device__ __forceinline__ void split_val(float v, bf16& h, bf16& l) {
    h = __float2bfloat16(v);
    l = __float2bfloat16(v - __bfloat162float(h));
}

// ---------------------------------------------------------------------------
// SMEM: 2 stages x (Ah 32K | Al 32K | Bh 16K | Bl 16K) = 192 KB
// A slab: 256 rows x 128B (64 bf16, k-major).  B k-major: 128 rows x 128B.
// B n-major (out-kernel V): 64 k-rows x 256B (128 bf16 cols).
// ---------------------------------------------------------------------------
static constexpr int ASLAB = 32768;
static constexpr int BSLAB = 16384;
static constexpr int STAGE = 2 * ASLAB + 2 * BSLAB;   // 98304
static constexpr int SMEM_TOTAL = 2 * STAGE;          // 196608

// Loaders for 512 threads (t = 0..511).
__device__ __forceinline__ void load_A(const bf16* src, size_t ld, uint32_t sbase, int t)
{
    const int col = t & 7, r0 = t >> 3;           // r0: 0..63
    #pragma unroll
    for (int p = 0; p < 4; p++) {
        const int row = r0 + 64 * p;
        const uint32_t off = row * 128 + ((col ^ (row & 7)) << 4);
        cp16(sbase + off, src + (size_t)row * ld + col * 8);
    }
}
__device__ __forceinline__ void load_Bk(const bf16* src, size_t ld, uint32_t sbase, int t)
{
    const int col = t & 7, r0 = t >> 3;           // r0: 0..63
    #pragma unroll
    for (int p = 0; p < 2; p++) {
        const int row = r0 + 64 * p;
        const uint32_t off = row * 128 + ((col ^ (row & 7)) << 4);
        cp16(sbase + off, src + (size_t)row * ld + col * 8);
    }
}
__device__ __forceinline__ void load_Bn(const bf16* src, size_t ld, uint32_t sbase, int t)
{
    const int col = t & 15, r0 = t >> 4;          // r0: 0..31
    #pragma unroll
    for (int p = 0; p < 2; p++) {
        const int row = r0 + 32 * p;
        const uint32_t off = row * 256 + ((col ^ (row & 7)) << 4);
        cp16(sbase + off, src + (size_t)row * ld + col * 8);
    }
}

// 3-product split MMA over one 64-k chunk; warp tile 64(m) x 32(n).
// Warp grid: 4(m) x 4(n).  B slab k-major.
__device__ __forceinline__ void compute_nt(uint32_t base, float c[4][4][4],
                                           int lane, int wm0, int wn0)
{
    const uint32_t sAh = base, sAl = base + ASLAB;
    const uint32_t sBh = base + 2 * ASLAB, sBl = sBh + BSLAB;
    #pragma unroll
    for (int kk = 0; kk < 4; kk++) {
        uint32_t aH[4][4], aL[4][4];
        const int ar = lane & 15;
        const int ac = 2 * kk + (lane >> 4);
        #pragma unroll
        for (int i = 0; i < 4; i++) {
            const int row = wm0 + i * 16 + ar;
            const uint32_t off = row * 128 + ((ac ^ (row & 7)) << 4);
            ldsm4(aH[i], sAh + off);
            ldsm4(aL[i], sAl + off);
        }
        const int br = (lane & 7) + ((lane >> 4) & 1) * 8;
        const int bc = 2 * kk + ((lane >> 3) & 1);
        #pragma unroll
        for (int jj = 0; jj < 2; jj++) {
            const int row = wn0 + jj * 16 + br;
            const uint32_t off = row * 128 + ((bc ^ (row & 7)) << 4);
            uint32_t tH[4], tL[4];
            ldsm4(tH, sBh + off);
            ldsm4(tL, sBl + off);
            uint32_t b0H[2] = {tH[0], tH[1]}, b1H[2] = {tH[2], tH[3]};
            uint32_t b0L[2] = {tL[0], tL[1]}, b1L[2] = {tL[2], tL[3]};
            #pragma unroll
            for (int i = 0; i < 4; i++) {
                mma16816(c[i][2 * jj], aH[i], b0H);
                mma16816(c[i][2 * jj], aH[i], b0L);
                mma16816(c[i][2 * jj], aL[i], b0H);
                mma16816(c[i][2 * jj + 1], aH[i], b1H);
                mma16816(c[i][2 * jj + 1], aH[i], b1L);
                mma16816(c[i][2 * jj + 1], aL[i], b1H);
            }
        }
    }
}

// Same, B slab n-major via ldmatrix.trans.
__device__ __forceinline__ void compute_tr(uint32_t base, float c[4][4][4],
                                           int lane, int wm0, int wn0)
{
    const uint32_t sAh = base, sAl = base + ASLAB;
    const uint32_t sBh = base + 2 * ASLAB, sBl = sBh + BSLAB;
    #pragma unroll
    for (int kk = 0; kk < 4; kk++) {
        uint32_t aH[4][4], aL[4][4];
        const int ar = lane & 15;
        const int ac = 2 * kk + (lane >> 4);
        #pragma unroll
        for (int i = 0; i < 4; i++) {
            const int row = wm0 + i * 16 + ar;
            const uint32_t off = row * 128 + ((ac ^ (row & 7)) << 4);
            ldsm4(aH[i], sAh + off);
            ldsm4(aL[i], sAl + off);
        }
        const int br = kk * 16 + (lane & 7) + ((lane >> 3) & 1) * 8;
        #pragma unroll
        for (int jj = 0; jj < 2; jj++) {
            const int ch = (wn0 >> 3) + 2 * jj + (lane >> 4);
            const uint32_t off = br * 256 + ((ch ^ (br & 7)) << 4);
            uint32_t tH[4], tL[4];
            ldsm4t(tH, sBh + off);
            ldsm4t(tL, sBl + off);
            uint32_t b0H[2] = {tH[0], tH[1]}, b1H[2] = {tH[2], tH[3]};
            uint32_t b0L[2] = {tL[0], tL[1]}, b1L[2] = {tL[2], tL[3]};
            #pragma unroll
            for (int i = 0; i < 4; i++) {
                mma16816(c[i][2 * jj], aH[i], b0H);
                mma16816(c[i][2 * jj], aH[i], b0L);
                mma16816(c[i][2 * jj], aL[i], b0H);
                mma16816(c[i][2 * jj + 1], aH[i], b1H);
                mma16816(c[i][2 * jj + 1], aH[i], b1L);
                mma16816(c[i][2 * jj + 1], aL[i], b1H);
            }
        }
    }
}

#define ZERO_ACC(c)                                  \
    _Pragma("unroll")                                \
    for (int i = 0; i < 4; i++)                      \
        _Pragma("unroll")                            \
        for (int j = 0; j < 4; j++)                  \
            _Pragma("unroll")                        \
            for (int k = 0; k < 4; k++) c[i][j][k] = 0.f;

// ---------------------------------------------------------------------------
// Kernel 1: QKV projections. CTA tile 256(m) x 128(n), 512 threads.
// ---------------------------------------------------------------------------
__global__ __launch_bounds__(512, 1)
void qkv_mma_kernel(const float* __restrict__ bq, const float* __restrict__ bk,
                    const float* __restrict__ bv)
{
    extern __shared__ char smem[];
    const uint32_t sb = smem_to_u32(smem);
    const int tid = threadIdx.x, wid = tid >> 5, lane = tid & 31;
    const int wm0 = (wid & 3) * 64, wn0 = (wid >> 2) * 32;

    const int n0 = blockIdx.x * 128, m0 = blockIdx.y * 256, z = blockIdx.z;
    const bf16 *Wh_, *Wl_;
    const float* bias;
    bf16 *Dh, *Dl;
    if (z == 0)      { Wh_ = g_wqh; Wl_ = g_wql; bias = bq; Dh = g_Qh; Dl = g_Ql; }
    else if (z == 1) { Wh_ = g_wkh; Wl_ = g_wkl; bias = bk; Dh = g_Kh; Dl = g_Kl; }
    else             { Wh_ = g_wvh; Wl_ = g_wvl; bias = bv; Dh = g_Vh; Dl = g_Vl; }

    const bf16* Ah = g_xh + (size_t)m0 * DDIM;
    const bf16* Al = g_xl + (size_t)m0 * DDIM;
    const bf16* Bh = Wh_ + (size_t)n0 * DDIM;
    const bf16* Bl = Wl_ + (size_t)n0 * DDIM;

    const int NIT = DDIM / 64;
    load_A(Ah, DDIM, sb, tid);
    load_A(Al, DDIM, sb + ASLAB, tid);
    load_Bk(Bh, DDIM, sb + 2 * ASLAB, tid);
    load_Bk(Bl, DDIM, sb + 2 * ASLAB + BSLAB, tid);
    cp_commit();

    float c[4][4][4];
    ZERO_ACC(c);

    for (int it = 0; it < NIT; it++) {
        if (it + 1 < NIT) {
            const uint32_t d = sb + ((it + 1) & 1) * STAGE;
            const size_t ko = (size_t)(it + 1) * 64;
            load_A(Ah + ko, DDIM, d, tid);
            load_A(Al + ko, DDIM, d + ASLAB, tid);
            load_Bk(Bh + ko, DDIM, d + 2 * ASLAB, tid);
            load_Bk(Bl + ko, DDIM, d + 2 * ASLAB + BSLAB, tid);
            cp_commit();
            cp_wait1();
        } else cp_wait0();
        __syncthreads();
        compute_nt(sb + (it & 1) * STAGE, c, lane, wm0, wn0);
        __syncthreads();
    }

    #pragma unroll
    for (int i = 0; i < 4; i++)
        #pragma unroll
        for (int h = 0; h < 2; h++) {
            const int m = m0 + wm0 + i * 16 + (lane >> 2) + 8 * h;
            #pragma unroll
            for (int j = 0; j < 4; j++) {
                const int col = n0 + wn0 + j * 8 + 2 * (lane & 3);
                const float2 bs = *(const float2*)(bias + col);
                const float v0 = c[i][j][2 * h] + bs.x;
                const float v1 = c[i][j][2 * h + 1] + bs.y;
                bf16 h0, h1, l0, l1;
                split_val(v0, h0, l0);
                split_val(v1, h1, l1);
                const size_t idx = (size_t)m * DDIM + col;
                *(uint32_t*)(Dh + idx) = pack_bf16(h0, h1);
                *(uint32_t*)(Dl + idx) = pack_bf16(l0, l1);
            }
        }
}

// ---------------------------------------------------------------------------
// Kernel 2: scores + mask*exp + split store W + fused rowsum atomics.
// CTA tile 256(q) x 128(c), 512 threads.
// ---------------------------------------------------------------------------
__global__ __launch_bounds__(512, 1)
void score_mma_kernel(const float* __restrict__ adj)
{
    extern __shared__ char smem[];
    const uint32_t sb = smem_to_u32(smem);
    const int tid = threadIdx.x, wid = tid >> 5, lane = tid & 31;
    const int wm0 = (wid & 3) * 64, wn0 = (wid >> 2) * 32;

    const int c0 = blockIdx.x * 128, q0 = blockIdx.y * 256, b = blockIdx.z;

    const bf16* Ah = g_Qh + ((size_t)b * NN + q0) * DDIM;
    const bf16* Al = g_Ql + ((size_t)b * NN + q0) * DDIM;
    const bf16* Bh = g_Kh + ((size_t)b * NN + c0) * DDIM;
    const bf16* Bl = g_Kl + ((size_t)b * NN + c0) * DDIM;

    const int NIT = DDIM / 64;
    load_A(Ah, DDIM, sb, tid);
    load_A(Al, DDIM, sb + ASLAB, tid);
    load_Bk(Bh, DDIM, sb + 2 * ASLAB, tid);
    load_Bk(Bl, DDIM, sb + 2 * ASLAB + BSLAB, tid);
    cp_commit();

    float c[4][4][4];
    ZERO_ACC(c);

    for (int it = 0; it < NIT; it++) {
        if (it + 1 < NIT) {
            const uint32_t d = sb + ((it + 1) & 1) * STAGE;
            const size_t ko = (size_t)(it + 1) * 64;
            load_A(Ah + ko, DDIM, d, tid);
            load_A(Al + ko, DDIM, d + ASLAB, tid);
            load_Bk(Bh + ko, DDIM, d + 2 * ASLAB, tid);
            load_Bk(Bl + ko, DDIM, d + 2 * ASLAB + BSLAB, tid);
            cp_commit();
            cp_wait1();
        } else cp_wait0();
        __syncthreads();
        compute_nt(sb + (it & 1) * STAGE, c, lane, wm0, wn0);
        __syncthreads();
    }

    #pragma unroll
    for (int i = 0; i < 4; i++)
        #pragma unroll
        for (int h = 0; h < 2; h++) {
            const int r = q0 + wm0 + i * 16 + (lane >> 2) + 8 * h;
            const size_t rowbase = ((size_t)b * NN + r) * NN;
            float rsum = 0.f;
            #pragma unroll
            for (int j = 0; j < 4; j++) {
                const int cc = c0 + wn0 + j * 8 + 2 * (lane & 3);
                const float2 a2 = *(const float2*)(adj + rowbase + cc);
                const float w0 = a2.x * __expf(c[i][j][2 * h]);
                const float w1 = a2.y * __expf(c[i][j][2 * h + 1]);
                rsum += w0 + w1;
                bf16 h0, h1, l0, l1;
                split_val(w0, h0, l0);
                split_val(w1, h1, l1);
                *(uint32_t*)(g_Wmh + rowbase + cc) = pack_bf16(h0, h1);
                *(uint32_t*)(g_Wml + rowbase + cc) = pack_bf16(l0, l1);
            }
            rsum += __shfl_xor_sync(0xffffffffu, rsum, 1);
            rsum += __shfl_xor_sync(0xffffffffu, rsum, 2);
            if ((lane & 3) == 0)
                atomicAdd(&g_rs[b * NN + r], rsum);
        }
}

// ---------------------------------------------------------------------------
// Kernel 3: O = (W @ V) / rowsum.  CTA tile 256(q) x 128(n), 512 threads.
// ---------------------------------------------------------------------------
__global__ __launch_bounds__(512, 1)
void out_mma_kernel(float* __restrict__ out)
{
    extern __shared__ char smem[];
    const uint32_t sb = smem_to_u32(smem);
    const int tid = threadIdx.x, wid = tid >> 5, lane = tid & 31;
    const int wm0 = (wid & 3) * 64, wn0 = (wid >> 2) * 32;

    const int n0 = blockIdx.x * 128, q0 = blockIdx.y * 256, b = blockIdx.z;

    const bf16* Ah = g_Wmh + ((size_t)b * NN + q0) * NN;
    const bf16* Al = g_Wml + ((size_t)b * NN + q0) * NN;
    const bf16* Bh = g_Vh + (size_t)b * NN * DDIM + n0;
    const bf16* Bl = g_Vl + (size_t)b * NN * DDIM + n0;

    const int NIT = NN / 64;
    load_A(Ah, NN, sb, tid);
    load_A(Al, NN, sb + ASLAB, tid);
    load_Bn(Bh, DDIM, sb + 2 * ASLAB, tid);
    load_Bn(Bl, DDIM, sb + 2 * ASLAB + BSLAB, tid);
    cp_commit();

    float c[4][4][4];
    ZERO_ACC(c);

    for (int it = 0; it < NIT; it++) {
        if (it + 1 < NIT) {
            const uint32_t d = sb + ((it + 1) & 1) * STAGE;
            const size_t ko = (size_t)(it + 1) * 64;
            load_A(Ah + ko, NN, d, tid);
            load_A(Al + ko, NN, d + ASLAB, tid);
            load_Bn(Bh + ko * DDIM, DDIM, d + 2 * ASLAB, tid);
            load_Bn(Bl + ko * DDIM, DDIM, d + 2 * ASLAB + BSLAB, tid);
            cp_commit();
            cp_wait1();
        } else cp_wait0();
        __syncthreads();
        compute_tr(sb + (it & 1) * STAGE, c, lane, wm0, wn0);
        __syncthreads();
    }

    #pragma unroll
    for (int i = 0; i < 4; i++)
        #pragma unroll
        for (int h = 0; h < 2; h++) {
            const int r = q0 + wm0 + i * 16 + (lane >> 2) + 8 * h;
            const float inv = 1.0f / g_rs[b * NN + r];
            float* op = out + ((size_t)b * NN + r) * DDIM;
            #pragma unroll
            for (int j = 0; j < 4; j++) {
                const int col = n0 + wn0 + j * 8 + 2 * (lane & 3);
                float2 v;
                v.x = c[i][j][2 * h] * inv;
                v.y = c[i][j][2 * h + 1] * inv;
                *(float2*)(op + col) = v;
            }
        }
}

// ---------------------------------------------------------------------------
// Elementwise: fp32 -> (hi, lo) bf16 split;  rowsum zero
// ---------------------------------------------------------------------------
__global__ void split_kernel(const float* __restrict__ src,
                             bf16* __restrict__ h, bf16* __restrict__ l, int n4)
{
    int i = blockIdx.x * blockDim.x + threadIdx.x;
    if (i >= n4) return;
    float4 v = ((const float4*)src)[i];
    bf16 h0, h1, h2, h3, l0, l1, l2, l3;
    split_val(v.x, h0, l0); split_val(v.y, h1, l1);
    split_val(v.z, h2, l2); split_val(v.w, h3, l3);
    ((uint2*)h)[i] = make_uint2(pack_bf16(h0, h1), pack_bf16(h2, h3));
    ((uint2*)l)[i] = make_uint2(pack_bf16(l0, l1), pack_bf16(l2, l3));
}

__global__ void zero_rs_kernel() {
    g_rs[blockIdx.x * 256 + threadIdx.x] = 0.f;
}

// ---------------------------------------------------------------------------
extern "C" void kernel_launch(void* const* d_in, const int* in_sizes, int n_in,
                              void* d_out, int out_size)
{
    const float* x    = (const float*)d_in[0];
    const float* adj  = (const float*)d_in[1];
    const float* Wq_w = (const float*)d_in[2];
    const float* Wq_b = (const float*)d_in[3];
    const float* Wk_w = (const float*)d_in[4];
    const float* Wk_b = (const float*)d_in[5];
    const float* Wv_w = (const float*)d_in[6];
    const float* Wv_b = (const float*)d_in[7];
    float* out = (float*)d_out;

    cudaFuncSetAttribute(qkv_mma_kernel, cudaFuncAttributeMaxDynamicSharedMemorySize, SMEM_TOTAL);
    cudaFuncSetAttribute(score_mma_kernel, cudaFuncAttributeMaxDynamicSharedMemorySize, SMEM_TOTAL);
    cudaFuncSetAttribute(out_mma_kernel, cudaFuncAttributeMaxDynamicSharedMemorySize, SMEM_TOTAL);

    bf16 *xh, *xl, *wqh, *wql, *wkh, *wkl, *wvh, *wvl;
    cudaGetSymbolAddress((void**)&xh, g_xh);   cudaGetSymbolAddress((void**)&xl, g_xl);
    cudaGetSymbolAddress((void**)&wqh, g_wqh); cudaGetSymbolAddress((void**)&wql, g_wql);
    cudaGetSymbolAddress((void**)&wkh, g_wkh); cudaGetSymbolAddress((void**)&wkl, g_wkl);
    cudaGetSymbolAddress((void**)&wvh, g_wvh); cudaGetSymbolAddress((void**)&wvl, g_wvl);

    {
        int n4 = BB * NN * DDIM / 4;
        split_kernel<<<(n4 + 255) / 256, 256>>>(x, xh, xl, n4);
        int w4 = DDIM * DDIM / 4;
        split_kernel<<<(w4 + 255) / 256, 256>>>(Wq_w, wqh, wql, w4);
        split_kernel<<<(w4 + 255) / 256, 256>>>(Wk_w, wkh, wkl, w4);
        split_kernel<<<(w4 + 255) / 256, 256>>>(Wv_w, wvh, wvl, w4);
    }
    zero_rs_kernel<<<(BB * NN) / 256, 256>>>();

    {
        dim3 grid(DDIM / 128, BB * NN / 256, 3);
        qkv_mma_kernel<<<grid, 512, SMEM_TOTAL>>>(Wq_b, Wk_b, Wv_b);
    }
    {
        dim3 grid(NN / 128, NN / 256, BB);
        score_mma_kernel<<<grid, 512, SMEM_TOTAL>>>(adj);
    }
    {
        dim3 grid(DDIM / 128, NN / 256, BB);
        out_mma_kernel<<<grid, 512, SMEM_TOTAL>>>(out);
    }
}